// round 1
// baseline (speedup 1.0000x reference)
#include <cuda_runtime.h>

#define B 2
#define L 1536
#define D 768
#define H 12
#define DK 64

// Scratch (allocation-free rule: static __device__ arrays)
__device__ float g_qp[(size_t)B * L * D];                  // 9.4 MB
__device__ float g_kp[(size_t)B * L * D];                  // 9.4 MB
__device__ float g_s[(size_t)B * H * L * L];               // 226.5 MB, z = qk/16

// ---------------------------------------------------------------------------
// Phase 1: projection  C[M=B*L, N=D] = X @ W^T + bias   (fp32)
// 64x64 tile, 256 threads, 4x4 per thread, K-chunks of 16
// ---------------------------------------------------------------------------
__global__ void proj_kernel(const float* __restrict__ X,
                            const float* __restrict__ W,
                            const float* __restrict__ bias,
                            int which)
{
    __shared__ float As[64][17];
    __shared__ float Ws[64][17];

    float* out = which ? g_kp : g_qp;

    int bx = blockIdx.x;            // N tile (0..11)
    int by = blockIdx.y;            // M tile (0..47)
    int tid = threadIdx.x;
    int lrow = tid >> 2;            // 0..63
    int lcol = (tid & 3) * 4;       // 0,4,8,12
    int tx = tid & 15, ty = tid >> 4;

    const float* Ab = X + (size_t)(by * 64 + lrow) * D;
    const float* Wb = W + (size_t)(bx * 64 + lrow) * D;

    float acc[4][4];
    #pragma unroll
    for (int i = 0; i < 4; i++)
        #pragma unroll
        for (int j = 0; j < 4; j++) acc[i][j] = 0.f;

    for (int kc = 0; kc < D; kc += 16) {
        float4 av = *(const float4*)(Ab + kc + lcol);
        float4 wv = *(const float4*)(Wb + kc + lcol);
        __syncthreads();
        As[lrow][lcol + 0] = av.x; As[lrow][lcol + 1] = av.y;
        As[lrow][lcol + 2] = av.z; As[lrow][lcol + 3] = av.w;
        Ws[lrow][lcol + 0] = wv.x; Ws[lrow][lcol + 1] = wv.y;
        Ws[lrow][lcol + 2] = wv.z; Ws[lrow][lcol + 3] = wv.w;
        __syncthreads();
        #pragma unroll
        for (int kk = 0; kk < 16; kk++) {
            float a[4], w[4];
            #pragma unroll
            for (int i = 0; i < 4; i++) a[i] = As[ty * 4 + i][kk];
            #pragma unroll
            for (int j = 0; j < 4; j++) w[j] = Ws[tx * 4 + j][kk];
            #pragma unroll
            for (int i = 0; i < 4; i++)
                #pragma unroll
                for (int j = 0; j < 4; j++)
                    acc[i][j] = fmaf(a[i], w[j], acc[i][j]);
        }
    }

    #pragma unroll
    for (int i = 0; i < 4; i++) {
        int m = by * 64 + ty * 4 + i;
        #pragma unroll
        for (int j = 0; j < 4; j++) {
            int n = bx * 64 + tx * 4 + j;
            out[(size_t)m * D + n] = acc[i][j] + bias[n];
        }
    }
}

// ---------------------------------------------------------------------------
// Phase 2: scores  z[b,h,q,k] = (Qh . Kh) / 16   (fp32, K=64 fully in smem)
// grid (ktile=24, qtile=24, bh=24), 64x64 tile, 4x4 per thread
// ---------------------------------------------------------------------------
__global__ void scores_kernel()
{
    __shared__ float Qs[64][65];
    __shared__ float Ks[64][65];

    int kt = blockIdx.x, qt = blockIdx.y, bh = blockIdx.z;
    int b = bh / H, h = bh % H;
    int tid = threadIdx.x;
    int tx = tid & 15, ty = tid >> 4;

    // load 64x64 Q and K tiles (each thread: 4 float4 per tile)
    #pragma unroll
    for (int rr = 0; rr < 4; rr++) {
        int row = (tid >> 4) + rr * 16;
        int c4  = (tid & 15) * 4;
        float4 qv = *(const float4*)(g_qp + (size_t)(b * L + qt * 64 + row) * D + h * DK + c4);
        float4 kv = *(const float4*)(g_kp + (size_t)(b * L + kt * 64 + row) * D + h * DK + c4);
        Qs[row][c4 + 0] = qv.x; Qs[row][c4 + 1] = qv.y;
        Qs[row][c4 + 2] = qv.z; Qs[row][c4 + 3] = qv.w;
        Ks[row][c4 + 0] = kv.x; Ks[row][c4 + 1] = kv.y;
        Ks[row][c4 + 2] = kv.z; Ks[row][c4 + 3] = kv.w;
    }
    __syncthreads();

    float acc[4][4];
    #pragma unroll
    for (int i = 0; i < 4; i++)
        #pragma unroll
        for (int j = 0; j < 4; j++) acc[i][j] = 0.f;

    #pragma unroll 8
    for (int kk = 0; kk < 64; kk++) {
        float a[4], w[4];
        #pragma unroll
        for (int i = 0; i < 4; i++) a[i] = Qs[ty * 4 + i][kk];
        #pragma unroll
        for (int j = 0; j < 4; j++) w[j] = Ks[tx * 4 + j][kk];
        #pragma unroll
        for (int i = 0; i < 4; i++)
            #pragma unroll
            for (int j = 0; j < 4; j++)
                acc[i][j] = fmaf(a[i], w[j], acc[i][j]);
    }

    const float scale = 1.0f / 16.0f;   // 1/(2*sqrt(64)): folds entmax z = scores/2
    #pragma unroll
    for (int i = 0; i < 4; i++) {
        size_t rbase = ((size_t)bh * L + qt * 64 + ty * 4 + i) * L + kt * 64;
        #pragma unroll
        for (int j = 0; j < 4; j++)
            g_s[rbase + tx * 4 + j] = acc[i][j] * scale;
    }
}

// ---------------------------------------------------------------------------
// Phase 3: entmax-1.5 per (b,h,q) row via Newton on sum((z-tau)_+^2)=1,
// accumulated over heads. One block per (b,q). 256 thr x 6 vals.
// ---------------------------------------------------------------------------
#define NT 256
#define VPT 6

__device__ __forceinline__ float blockMax(float v)
{
    __shared__ float sh[8];
    #pragma unroll
    for (int o = 16; o; o >>= 1) v = fmaxf(v, __shfl_xor_sync(0xffffffffu, v, o));
    if ((threadIdx.x & 31) == 0) sh[threadIdx.x >> 5] = v;
    __syncthreads();
    if (threadIdx.x < 32) {
        float m = (threadIdx.x < 8) ? sh[threadIdx.x] : -3.4e38f;
        #pragma unroll
        for (int o = 4; o; o >>= 1) m = fmaxf(m, __shfl_xor_sync(0xffffffffu, m, o));
        if (threadIdx.x == 0) sh[0] = m;
    }
    __syncthreads();
    float r = sh[0];
    __syncthreads();
    return r;
}

__device__ __forceinline__ void blockSum2(float& a, float& b)
{
    __shared__ float sa[8], sb[8];
    #pragma unroll
    for (int o = 16; o; o >>= 1) {
        a += __shfl_xor_sync(0xffffffffu, a, o);
        b += __shfl_xor_sync(0xffffffffu, b, o);
    }
    if ((threadIdx.x & 31) == 0) { sa[threadIdx.x >> 5] = a; sb[threadIdx.x >> 5] = b; }
    __syncthreads();
    if (threadIdx.x < 32) {
        float x = (threadIdx.x < 8) ? sa[threadIdx.x] : 0.f;
        float y = (threadIdx.x < 8) ? sb[threadIdx.x] : 0.f;
        #pragma unroll
        for (int o = 4; o; o >>= 1) {
            x += __shfl_xor_sync(0xffffffffu, x, o);
            y += __shfl_xor_sync(0xffffffffu, y, o);
        }
        if (threadIdx.x == 0) { sa[0] = x; sb[0] = y; }
    }
    __syncthreads();
    a = sa[0]; b = sb[0];
    __syncthreads();
}

__global__ void entmax_kernel(const int* __restrict__ mask, float* __restrict__ out)
{
    int b  = blockIdx.x / L;
    int qi = blockIdx.x % L;
    int t  = threadIdx.x;

    bool valid[VPT];
    float acc[VPT];
    #pragma unroll
    for (int i = 0; i < VPT; i++) {
        acc[i] = 0.f;
        valid[i] = (mask[b * L + t + i * NT] != 0);
    }

    const float invH = 1.0f / 12.0f;

    for (int h = 0; h < H; h++) {
        const float* row = g_s + ((size_t)(b * H + h) * L + qi) * L;
        float z[VPT];
        float m = -1e30f;
        #pragma unroll
        for (int i = 0; i < VPT; i++) {
            z[i] = valid[i] ? row[t + i * NT] : -1e30f;
            m = fmaxf(m, z[i]);
        }
        float zmax = blockMax(m);
        float tau = zmax - 1.0f;     // f(tau0) >= 0, Newton from left is monotone

        for (int it = 0; it < 32; it++) {
            float s0 = 0.f, s1 = 0.f;
            #pragma unroll
            for (int i = 0; i < VPT; i++) {
                float d = z[i] - tau;
                if (d > 0.f) { s0 = fmaf(d, d, s0); s1 += d; }
            }
            blockSum2(s0, s1);
            if (s1 <= 0.f) break;
            float step = (s0 - 1.0f) / (2.0f * s1);
            tau += step;
            if (fabsf(step) <= 1e-6f) break;
        }

        #pragma unroll
        for (int i = 0; i < VPT; i++) {
            float d = z[i] - tau;
            if (d > 0.f) acc[i] = fmaf(d * d, invH, acc[i]);
        }
    }

    float* orow = out + ((size_t)b * L + qi) * L;
    #pragma unroll
    for (int i = 0; i < VPT; i++)
        orow[t + i * NT] = acc[i];
}

// ---------------------------------------------------------------------------
extern "C" void kernel_launch(void* const* d_in, const int* in_sizes, int n_in,
                              void* d_out, int out_size)
{
    const float* query = (const float*)d_in[0];
    const float* key   = (const float*)d_in[1];
    const int*   mask  = (const int*)d_in[2];
    const float* wq_w  = (const float*)d_in[3];
    const float* wq_b  = (const float*)d_in[4];
    const float* wk_w  = (const float*)d_in[5];
    const float* wk_b  = (const float*)d_in[6];
    float* out = (float*)d_out;

    (void)in_sizes; (void)n_in; (void)out_size;

    dim3 pgrid(D / 64, (B * L) / 64);          // (12, 48)
    proj_kernel<<<pgrid, 256>>>(query, wq_w, wq_b, 0);
    proj_kernel<<<pgrid, 256>>>(key,   wk_w, wk_b, 1);

    dim3 sgrid(L / 64, L / 64, B * H);         // (24, 24, 24)
    scores_kernel<<<sgrid, 256>>>();

    entmax_kernel<<<B * L, NT>>>(mask, out);
}

// round 3
// speedup vs baseline: 1.6401x; 1.6401x over previous
#include <cuda_runtime.h>
#include <cuda_bf16.h>
#include <cstdint>

#define B 2
#define L 1536
#define D 768
#define H 12
#define DK 64

// ---------------------------------------------------------------------------
// Scratch (allocation-free rule: static __device__ arrays)
// ---------------------------------------------------------------------------
__device__ float g_qp[(size_t)B * L * D];                   // fp32 Q proj
__device__ float g_kp[(size_t)B * L * D];                   // fp32 K proj
__device__ __nv_bfloat16 g_qh[(size_t)B * L * D];           // bf16 hi/lo splits
__device__ __nv_bfloat16 g_ql[(size_t)B * L * D];
__device__ __nv_bfloat16 g_kh[(size_t)B * L * D];
__device__ __nv_bfloat16 g_kl[(size_t)B * L * D];
__device__ float g_s[(size_t)B * H * L * L];                // 226.5 MB, z = qk/16

__device__ __forceinline__ uint32_t smem_u32(const void* p) {
    uint32_t a;
    asm("{ .reg .u64 t; cvta.to.shared.u64 t, %1; cvt.u32.u64 %0, t; }" : "=r"(a) : "l"(p));
    return a;
}

// ---------------------------------------------------------------------------
// Phase 1: projection  C[M=B*L, N=D] = X @ W^T + bias   (fp32)
// ---------------------------------------------------------------------------
__global__ void proj_kernel(const float* __restrict__ X,
                            const float* __restrict__ W,
                            const float* __restrict__ bias,
                            int which)
{
    __shared__ float As[64][17];
    __shared__ float Ws[64][17];

    float* out = which ? g_kp : g_qp;

    int bx = blockIdx.x, by = blockIdx.y;
    int tid = threadIdx.x;
    int lrow = tid >> 2;
    int lcol = (tid & 3) * 4;
    int tx = tid & 15, ty = tid >> 4;

    const float* Ab = X + (size_t)(by * 64 + lrow) * D;
    const float* Wb = W + (size_t)(bx * 64 + lrow) * D;

    float acc[4][4];
    #pragma unroll
    for (int i = 0; i < 4; i++)
        #pragma unroll
        for (int j = 0; j < 4; j++) acc[i][j] = 0.f;

    for (int kc = 0; kc < D; kc += 16) {
        float4 av = *(const float4*)(Ab + kc + lcol);
        float4 wv = *(const float4*)(Wb + kc + lcol);
        __syncthreads();
        As[lrow][lcol + 0] = av.x; As[lrow][lcol + 1] = av.y;
        As[lrow][lcol + 2] = av.z; As[lrow][lcol + 3] = av.w;
        Ws[lrow][lcol + 0] = wv.x; Ws[lrow][lcol + 1] = wv.y;
        Ws[lrow][lcol + 2] = wv.z; Ws[lrow][lcol + 3] = wv.w;
        __syncthreads();
        #pragma unroll
        for (int kk = 0; kk < 16; kk++) {
            float a[4], w[4];
            #pragma unroll
            for (int i = 0; i < 4; i++) a[i] = As[ty * 4 + i][kk];
            #pragma unroll
            for (int j = 0; j < 4; j++) w[j] = Ws[tx * 4 + j][kk];
            #pragma unroll
            for (int i = 0; i < 4; i++)
                #pragma unroll
                for (int j = 0; j < 4; j++)
                    acc[i][j] = fmaf(a[i], w[j], acc[i][j]);
        }
    }

    #pragma unroll
    for (int i = 0; i < 4; i++) {
        int m = by * 64 + ty * 4 + i;
        #pragma unroll
        for (int j = 0; j < 4; j++) {
            int n = bx * 64 + tx * 4 + j;
            out[(size_t)m * D + n] = acc[i][j] + bias[n];
        }
    }
}

// ---------------------------------------------------------------------------
// Phase 1.5: fp32 -> bf16 hi/lo split of both projections
// ---------------------------------------------------------------------------
__global__ void split_kernel()
{
    size_t n = (size_t)B * L * D;
    size_t i = (size_t)blockIdx.x * blockDim.x + threadIdx.x;
    if (i >= n / 4) return;

    const float4 q = *((const float4*)g_qp + i);
    const float4 k = *((const float4*)g_kp + i);
    __nv_bfloat16 qh[4], ql[4], kh[4], kl[4];
    const float* qf = &q.x; const float* kf = &k.x;
    #pragma unroll
    for (int j = 0; j < 4; j++) {
        qh[j] = __float2bfloat16(qf[j]);
        ql[j] = __float2bfloat16(qf[j] - __bfloat162float(qh[j]));
        kh[j] = __float2bfloat16(kf[j]);
        kl[j] = __float2bfloat16(kf[j] - __bfloat162float(kh[j]));
    }
    *((uint2*)g_qh + i) = *(uint2*)qh;
    *((uint2*)g_ql + i) = *(uint2*)ql;
    *((uint2*)g_kh + i) = *(uint2*)kh;
    *((uint2*)g_kl + i) = *(uint2*)kl;
}

// ---------------------------------------------------------------------------
// Phase 2: scores via warp-level mma.sync bf16 (3-term split).
// CTA tile 128(q) x 128(k) x 64(dk); 8 warps, each 64x32.
// z = (qh*kh + qh*kl + ql*kh) / 16
// ---------------------------------------------------------------------------
#define RP 72                    // padded row length in bf16 (144 B: conflict-free)
#define TILE_SM (128 * RP)       // elements per tile
#define SM_BYTES (4 * TILE_SM * 2)

__device__ __forceinline__ void ldsm_x4(uint32_t addr, uint32_t& r0, uint32_t& r1,
                                        uint32_t& r2, uint32_t& r3) {
    asm volatile("ldmatrix.sync.aligned.m8n8.x4.shared.b16 {%0,%1,%2,%3}, [%4];"
                 : "=r"(r0), "=r"(r1), "=r"(r2), "=r"(r3) : "r"(addr));
}
__device__ __forceinline__ void ldsm_x2(uint32_t addr, uint32_t& r0, uint32_t& r1) {
    asm volatile("ldmatrix.sync.aligned.m8n8.x2.shared.b16 {%0,%1}, [%2];"
                 : "=r"(r0), "=r"(r1) : "r"(addr));
}
__device__ __forceinline__ void mma_bf16(float* c, const uint32_t* a, const uint32_t* b) {
    asm volatile(
        "mma.sync.aligned.m16n8k16.row.col.f32.bf16.bf16.f32 "
        "{%0,%1,%2,%3}, {%4,%5,%6,%7}, {%8,%9}, {%0,%1,%2,%3};"
        : "+f"(c[0]), "+f"(c[1]), "+f"(c[2]), "+f"(c[3])
        : "r"(a[0]), "r"(a[1]), "r"(a[2]), "r"(a[3]), "r"(b[0]), "r"(b[1]));
}

__global__ void __launch_bounds__(256, 1) scores_mma_kernel()
{
    extern __shared__ __nv_bfloat16 sm[];
    __nv_bfloat16* sQh = sm;
    __nv_bfloat16* sQl = sm + TILE_SM;
    __nv_bfloat16* sKh = sm + 2 * TILE_SM;
    __nv_bfloat16* sKl = sm + 3 * TILE_SM;

    int kt = blockIdx.x, qt = blockIdx.y, bh = blockIdx.z;
    int b = bh / H, h = bh % H;
    int tid = threadIdx.x;
    int wid = tid >> 5, lane = tid & 31;

    // ---- load 4 tiles of 128 rows x 64 bf16 (128B rows) into padded smem ----
    {
        const __nv_bfloat16* qhb = g_qh + (size_t)(b * L + qt * 128) * D + h * DK;
        const __nv_bfloat16* qlb = g_ql + (size_t)(b * L + qt * 128) * D + h * DK;
        const __nv_bfloat16* khb = g_kh + (size_t)(b * L + kt * 128) * D + h * DK;
        const __nv_bfloat16* klb = g_kl + (size_t)(b * L + kt * 128) * D + h * DK;

        #pragma unroll
        for (int it = 0; it < 4; it++) {
            int idx = tid + it * 256;          // 0..1023
            int row = idx >> 3;
            int c8  = (idx & 7) * 8;           // bf16 element offset (16B chunks)
            *(uint4*)(sQh + row * RP + c8) = *(const uint4*)(qhb + (size_t)row * D + c8);
            *(uint4*)(sQl + row * RP + c8) = *(const uint4*)(qlb + (size_t)row * D + c8);
            *(uint4*)(sKh + row * RP + c8) = *(const uint4*)(khb + (size_t)row * D + c8);
            *(uint4*)(sKl + row * RP + c8) = *(const uint4*)(klb + (size_t)row * D + c8);
        }
    }
    __syncthreads();

    int wm = (wid & 1) * 64;                   // warp M offset (2 warps over M)
    int wn = (wid >> 1) * 32;                  // warp N offset (4 warps over N)

    float acc[4][4][4];                        // [m-frag][n-frag][4]
    #pragma unroll
    for (int i = 0; i < 4; i++)
        #pragma unroll
        for (int j = 0; j < 4; j++)
            #pragma unroll
            for (int r = 0; r < 4; r++) acc[i][j][r] = 0.f;

    uint32_t sQh_b = smem_u32(sQh), sQl_b = smem_u32(sQl);
    uint32_t sKh_b = smem_u32(sKh), sKl_b = smem_u32(sKl);

    // ldmatrix address components
    int a_row = lane & 15;                     // within m16
    int a_kh8 = (lane >> 4) * 8;               // k half for x4
    int b_row = lane & 7;                      // within n8
    int b_kh8 = ((lane >> 3) & 1) * 8;         // k half for x2

    #pragma unroll
    for (int ks = 0; ks < 4; ks++) {           // K steps of 16
        int kbase = ks * 16;
        uint32_t aqh[4][4], aql[4][4];
        uint32_t bkh[4][2], bkl[4][2];

        #pragma unroll
        for (int i = 0; i < 4; i++) {          // 4 m-frags (16 rows each)
            uint32_t off = (uint32_t)((wm + i * 16 + a_row) * RP + kbase + a_kh8) * 2;
            ldsm_x4(sQh_b + off, aqh[i][0], aqh[i][1], aqh[i][2], aqh[i][3]);
            ldsm_x4(sQl_b + off, aql[i][0], aql[i][1], aql[i][2], aql[i][3]);
        }
        #pragma unroll
        for (int j = 0; j < 4; j++) {          // 4 n-frags (8 rows each)
            uint32_t off = (uint32_t)((wn + j * 8 + b_row) * RP + kbase + b_kh8) * 2;
            ldsm_x2(sKh_b + off, bkh[j][0], bkh[j][1]);
            ldsm_x2(sKl_b + off, bkl[j][0], bkl[j][1]);
        }

        #pragma unroll
        for (int i = 0; i < 4; i++)
            #pragma unroll
            for (int j = 0; j < 4; j++) {
                mma_bf16(acc[i][j], aqh[i], bkh[j]);   // hi*hi
                mma_bf16(acc[i][j], aqh[i], bkl[j]);   // hi*lo
                mma_bf16(acc[i][j], aql[i], bkh[j]);   // lo*hi
            }
    }

    // ---- epilogue: scale and store fp32 scores ----
    const float scale = 1.0f / 16.0f;          // 1/(2*sqrt(dk)) folds entmax z=s/2
    int r0 = lane >> 2;
    int cp = (lane & 3) * 2;
    #pragma unroll
    for (int i = 0; i < 4; i++) {
        int grow0 = qt * 128 + wm + i * 16 + r0;
        #pragma unroll
        for (int j = 0; j < 4; j++) {
            int gcol = kt * 128 + wn + j * 8 + cp;
            float2 v0 = make_float2(acc[i][j][0] * scale, acc[i][j][1] * scale);
            float2 v1 = make_float2(acc[i][j][2] * scale, acc[i][j][3] * scale);
            *(float2*)(g_s + ((size_t)bh * L + grow0) * L + gcol) = v0;
            *(float2*)(g_s + ((size_t)bh * L + grow0 + 8) * L + gcol) = v1;
        }
    }
}

// ---------------------------------------------------------------------------
// Phase 3: entmax-1.5, one WARP per (b,q) row. 48 values/lane in registers.
// Newton on sum((z-tau)_+^2)=1, warp-shuffle reductions only.
// ---------------------------------------------------------------------------
__global__ void entmax_warp_kernel(const int* __restrict__ mask, float* __restrict__ out)
{
    int warp = (blockIdx.x * blockDim.x + threadIdx.x) >> 5;
    int lane = threadIdx.x & 31;
    int b = warp / L, qi = warp % L;

    unsigned long long vbits = 0ull;
    {
        const int4* mrow = (const int4*)(mask + b * L);
        #pragma unroll
        for (int i = 0; i < 12; i++) {
            int4 mv = mrow[lane + i * 32];
            if (mv.x) vbits |= 1ull << (i * 4 + 0);
            if (mv.y) vbits |= 1ull << (i * 4 + 1);
            if (mv.z) vbits |= 1ull << (i * 4 + 2);
            if (mv.w) vbits |= 1ull << (i * 4 + 3);
        }
    }

    float acc[48];
    #pragma unroll
    for (int e = 0; e < 48; e++) acc[e] = 0.f;

    const float invH = 1.0f / 12.0f;

    for (int h = 0; h < H; h++) {
        const float4* row = (const float4*)(g_s + ((size_t)(b * H + h) * L + qi) * L);
        float z[48];
        float m = -1e30f;
        #pragma unroll
        for (int i = 0; i < 12; i++) {
            float4 v = __ldg(row + lane + i * 32);
            z[i * 4 + 0] = (vbits >> (i * 4 + 0)) & 1 ? v.x : -1e30f;
            z[i * 4 + 1] = (vbits >> (i * 4 + 1)) & 1 ? v.y : -1e30f;
            z[i * 4 + 2] = (vbits >> (i * 4 + 2)) & 1 ? v.z : -1e30f;
            z[i * 4 + 3] = (vbits >> (i * 4 + 3)) & 1 ? v.w : -1e30f;
            m = fmaxf(m, fmaxf(fmaxf(z[i * 4], z[i * 4 + 1]), fmaxf(z[i * 4 + 2], z[i * 4 + 3])));
        }
        #pragma unroll
        for (int o = 16; o; o >>= 1) m = fmaxf(m, __shfl_xor_sync(0xffffffffu, m, o));

        float tau = m - 1.0f;   // f(tau0) >= 1: Newton from left, monotone convergence

        for (int it = 0; it < 24; it++) {
            float s0 = 0.f, s1 = 0.f;
            #pragma unroll
            for (int e = 0; e < 48; e++) {
                float d = z[e] - tau;
                if (d > 0.f) { s0 = fmaf(d, d, s0); s1 += d; }
            }
            #pragma unroll
            for (int o = 16; o; o >>= 1) {
                s0 += __shfl_xor_sync(0xffffffffu, s0, o);
                s1 += __shfl_xor_sync(0xffffffffu, s1, o);
            }
            if (s1 <= 0.f) break;
            float step = (s0 - 1.0f) / (2.0f * s1);
            tau += step;
            if (fabsf(step) <= 5e-7f) break;
        }

        #pragma unroll
        for (int e = 0; e < 48; e++) {
            float d = z[e] - tau;
            if (d > 0.f) acc[e] = fmaf(d * d, invH, acc[e]);
        }
    }

    float4* orow = (float4*)(out + ((size_t)b * L + qi) * L);
    #pragma unroll
    for (int i = 0; i < 12; i++) {
        float4 v;
        v.x = acc[i * 4 + 0]; v.y = acc[i * 4 + 1];
        v.z = acc[i * 4 + 2]; v.w = acc[i * 4 + 3];
        orow[lane + i * 32] = v;
    }
}

// ---------------------------------------------------------------------------
extern "C" void kernel_launch(void* const* d_in, const int* in_sizes, int n_in,
                              void* d_out, int out_size)
{
    const float* query = (const float*)d_in[0];
    const float* key   = (const float*)d_in[1];
    const int*   mask  = (const int*)d_in[2];
    const float* wq_w  = (const float*)d_in[3];
    const float* wq_b  = (const float*)d_in[4];
    const float* wk_w  = (const float*)d_in[5];
    const float* wk_b  = (const float*)d_in[6];
    float* out = (float*)d_out;

    (void)in_sizes; (void)n_in; (void)out_size;

    cudaFuncSetAttribute(scores_mma_kernel,
                         cudaFuncAttributeMaxDynamicSharedMemorySize, SM_BYTES);

    dim3 pgrid(D / 64, (B * L) / 64);            // (12, 48)
    proj_kernel<<<pgrid, 256>>>(query, wq_w, wq_b, 0);
    proj_kernel<<<pgrid, 256>>>(key,   wk_w, wk_b, 1);

    {
        size_t n4 = (size_t)B * L * D / 4;
        split_kernel<<<(unsigned)((n4 + 255) / 256), 256>>>();
    }

    dim3 sgrid(L / 128, L / 128, B * H);         // (12, 12, 24)
    scores_mma_kernel<<<sgrid, 256, SM_BYTES>>>();

    entmax_warp_kernel<<<(B * L) / 4, 128>>>(mask, out);
}

// round 4
// speedup vs baseline: 2.7006x; 1.6466x over previous
#include <cuda_runtime.h>
#include <cuda_bf16.h>
#include <cstdint>

#define B 2
#define L 1536
#define D 768
#define H 12
#define DK 64
#define BLD ((size_t)B * L * D)
#define DD  ((size_t)D * D)

// ---------------------------------------------------------------------------
// Scratch (allocation-free rule: static __device__ arrays)
// ---------------------------------------------------------------------------
// bf16 hi/lo splits of the raw inputs (consumed by proj)
__device__ __nv_bfloat16 g_xqh[BLD], g_xql[BLD];
__device__ __nv_bfloat16 g_xkh[BLD], g_xkl[BLD];
__device__ __nv_bfloat16 g_wqh[DD],  g_wql[DD];
__device__ __nv_bfloat16 g_wkh[DD],  g_wkl[DD];
// bf16 hi/lo splits of the projected Q/K (consumed by scores)
__device__ __nv_bfloat16 g_qh[BLD], g_ql[BLD];
__device__ __nv_bfloat16 g_kh[BLD], g_kl[BLD];
// fp32 scores z = qk/16
__device__ float g_s[(size_t)B * H * L * L];                // 226.5 MB

__device__ __forceinline__ uint32_t smem_u32(const void* p) {
    uint32_t a;
    asm("{ .reg .u64 t; cvta.to.shared.u64 t, %1; cvt.u32.u64 %0, t; }" : "=r"(a) : "l"(p));
    return a;
}

__device__ __forceinline__ void ldsm_x4(uint32_t addr, uint32_t& r0, uint32_t& r1,
                                        uint32_t& r2, uint32_t& r3) {
    asm volatile("ldmatrix.sync.aligned.m8n8.x4.shared.b16 {%0,%1,%2,%3}, [%4];"
                 : "=r"(r0), "=r"(r1), "=r"(r2), "=r"(r3) : "r"(addr));
}
__device__ __forceinline__ void ldsm_x2(uint32_t addr, uint32_t& r0, uint32_t& r1) {
    asm volatile("ldmatrix.sync.aligned.m8n8.x2.shared.b16 {%0,%1}, [%2];"
                 : "=r"(r0), "=r"(r1) : "r"(addr));
}
__device__ __forceinline__ void mma_bf16(float* c, const uint32_t* a, const uint32_t* b) {
    asm volatile(
        "mma.sync.aligned.m16n8k16.row.col.f32.bf16.bf16.f32 "
        "{%0,%1,%2,%3}, {%4,%5,%6,%7}, {%8,%9}, {%0,%1,%2,%3};"
        : "+f"(c[0]), "+f"(c[1]), "+f"(c[2]), "+f"(c[3])
        : "r"(a[0]), "r"(a[1]), "r"(a[2]), "r"(a[3]), "r"(b[0]), "r"(b[1]));
}

// ---------------------------------------------------------------------------
// Phase 0: fp32 -> bf16 hi/lo split of one source array (4 launches)
// which: 0=query, 1=key, 2=wq_w, 3=wk_w
// ---------------------------------------------------------------------------
__global__ void split_src_kernel(const float* __restrict__ src, int which, int n4)
{
    int i = blockIdx.x * blockDim.x + threadIdx.x;
    if (i >= n4) return;

    __nv_bfloat16* dh;
    __nv_bfloat16* dl;
    switch (which) {
        case 0: dh = g_xqh; dl = g_xql; break;
        case 1: dh = g_xkh; dl = g_xkl; break;
        case 2: dh = g_wqh; dl = g_wql; break;
        default: dh = g_wkh; dl = g_wkl; break;
    }

    float4 v = ((const float4*)src)[i];
    __nv_bfloat16 h[4], l[4];
    const float* f = &v.x;
    #pragma unroll
    for (int j = 0; j < 4; j++) {
        h[j] = __float2bfloat16(f[j]);
        l[j] = __float2bfloat16(f[j] - __bfloat162float(h[j]));
    }
    ((uint2*)dh)[i] = *(uint2*)h;
    ((uint2*)dl)[i] = *(uint2*)l;
}

// ---------------------------------------------------------------------------
// Phase 1: projection via HMMA bf16x3.
// C[M=3072, N=768] = X @ W^T + bias, output split to bf16 hi/lo.
// CTA tile 128(M) x 256(N), 512 thr (16 warps, warp 64x32), K chunks of 64.
// grid (3 ntiles, 24 mtiles, 2 which)
// ---------------------------------------------------------------------------
#define RP 72                           // padded row pitch (bf16) = 144B
#define PROJ_SM_A (128 * RP)            // per hi/lo tile
#define PROJ_SM_B (256 * RP)
#define PROJ_SM_BYTES ((2 * PROJ_SM_A + 2 * PROJ_SM_B) * 2)

__global__ void __launch_bounds__(512, 1) proj_mma_kernel(
    const float* __restrict__ biasq, const float* __restrict__ biask)
{
    extern __shared__ __nv_bfloat16 sm[];
    __nv_bfloat16* sAh = sm;
    __nv_bfloat16* sAl = sm + PROJ_SM_A;
    __nv_bfloat16* sBh = sm + 2 * PROJ_SM_A;
    __nv_bfloat16* sBl = sm + 2 * PROJ_SM_A + PROJ_SM_B;

    int nt = blockIdx.x, mt = blockIdx.y, which = blockIdx.z;
    int tid = threadIdx.x;
    int wid = tid >> 5, lane = tid & 31;

    const __nv_bfloat16* xh = which ? g_xkh : g_xqh;
    const __nv_bfloat16* xl = which ? g_xkl : g_xql;
    const __nv_bfloat16* wh = which ? g_wkh : g_wqh;
    const __nv_bfloat16* wl = which ? g_wkl : g_wql;
    __nv_bfloat16* oh = which ? g_kh : g_qh;
    __nv_bfloat16* ol = which ? g_kl : g_ql;
    const float* bias = which ? biask : biasq;

    int wm = (wid & 1) * 64;            // 2 warps over M(128)
    int wn = (wid >> 1) * 32;           // 8 warps over N(256)

    float acc[4][4][4];
    #pragma unroll
    for (int i = 0; i < 4; i++)
        #pragma unroll
        for (int j = 0; j < 4; j++)
            #pragma unroll
            for (int r = 0; r < 4; r++) acc[i][j][r] = 0.f;

    uint32_t sAh_b = smem_u32(sAh), sAl_b = smem_u32(sAl);
    uint32_t sBh_b = smem_u32(sBh), sBl_b = smem_u32(sBl);

    int a_row = lane & 15;
    int a_kh8 = (lane >> 4) * 8;
    int b_row = lane & 7;
    int b_kh8 = ((lane >> 3) & 1) * 8;

    for (int kc = 0; kc < D; kc += 64) {
        __syncthreads();
        // load A tile: 128 rows x 64 (hi+lo): 1024 uint4 each -> 2/thread
        #pragma unroll
        for (int it = 0; it < 2; it++) {
            int idx = tid + it * 512;
            int row = idx >> 3;
            int c8  = (idx & 7) * 8;
            size_t g = (size_t)(mt * 128 + row) * D + kc + c8;
            *(uint4*)(sAh + row * RP + c8) = *(const uint4*)(xh + g);
            *(uint4*)(sAl + row * RP + c8) = *(const uint4*)(xl + g);
        }
        // load B tile: 256 rows x 64 (hi+lo): 2048 uint4 each -> 4/thread
        #pragma unroll
        for (int it = 0; it < 4; it++) {
            int idx = tid + it * 512;
            int row = idx >> 3;
            int c8  = (idx & 7) * 8;
            size_t g = (size_t)(nt * 256 + row) * D + kc + c8;
            *(uint4*)(sBh + row * RP + c8) = *(const uint4*)(wh + g);
            *(uint4*)(sBl + row * RP + c8) = *(const uint4*)(wl + g);
        }
        __syncthreads();

        #pragma unroll
        for (int ks = 0; ks < 4; ks++) {
            int kb = ks * 16;
            uint32_t ah[4][4], al[4][4];
            #pragma unroll
            for (int i = 0; i < 4; i++) {
                uint32_t off = (uint32_t)((wm + i * 16 + a_row) * RP + kb + a_kh8) * 2;
                ldsm_x4(sAh_b + off, ah[i][0], ah[i][1], ah[i][2], ah[i][3]);
                ldsm_x4(sAl_b + off, al[i][0], al[i][1], al[i][2], al[i][3]);
            }
            #pragma unroll
            for (int j = 0; j < 4; j++) {
                uint32_t off = (uint32_t)((wn + j * 8 + b_row) * RP + kb + b_kh8) * 2;
                uint32_t bh[2], bl[2];
                ldsm_x2(sBh_b + off, bh[0], bh[1]);
                ldsm_x2(sBl_b + off, bl[0], bl[1]);
                #pragma unroll
                for (int i = 0; i < 4; i++) {
                    mma_bf16(acc[i][j], ah[i], bh);
                    mma_bf16(acc[i][j], ah[i], bl);
                    mma_bf16(acc[i][j], al[i], bh);
                }
            }
        }
    }

    // epilogue: + bias, split to bf16 hi/lo, store
    int r0 = lane >> 2;
    int cp = (lane & 3) * 2;
    #pragma unroll
    for (int i = 0; i < 4; i++) {
        int grow0 = mt * 128 + wm + i * 16 + r0;
        #pragma unroll
        for (int j = 0; j < 4; j++) {
            int gcol = nt * 256 + wn + j * 8 + cp;
            float2 bv = *(const float2*)(bias + gcol);
            #pragma unroll
            for (int half = 0; half < 2; half++) {
                float v0 = acc[i][j][half * 2 + 0] + bv.x;
                float v1 = acc[i][j][half * 2 + 1] + bv.y;
                __nv_bfloat16 h0 = __float2bfloat16(v0);
                __nv_bfloat16 h1 = __float2bfloat16(v1);
                __nv_bfloat16 l0 = __float2bfloat16(v0 - __bfloat162float(h0));
                __nv_bfloat16 l1 = __float2bfloat16(v1 - __bfloat162float(h1));
                size_t addr = (size_t)(grow0 + half * 8) * D + gcol;
                __nv_bfloat16 hp[2] = {h0, h1}, lp[2] = {l0, l1};
                *(uint32_t*)(oh + addr) = *(uint32_t*)hp;
                *(uint32_t*)(ol + addr) = *(uint32_t*)lp;
            }
        }
    }
}

// ---------------------------------------------------------------------------
// Phase 2: scores via HMMA bf16x3.  z = (qh*kh + qh*kl + ql*kh) / 16
// CTA tile 128(q) x 256(k) x 64(dk), 512 thr. grid (6 kt, 12 qt, 24 bh)
// ---------------------------------------------------------------------------
#define SC_SM_Q (128 * RP)
#define SC_SM_K (256 * RP)
#define SC_SM_BYTES ((2 * SC_SM_Q + 2 * SC_SM_K) * 2)

__global__ void __launch_bounds__(512, 1) scores_mma_kernel()
{
    extern __shared__ __nv_bfloat16 sm[];
    __nv_bfloat16* sQh = sm;
    __nv_bfloat16* sQl = sm + SC_SM_Q;
    __nv_bfloat16* sKh = sm + 2 * SC_SM_Q;
    __nv_bfloat16* sKl = sm + 2 * SC_SM_Q + SC_SM_K;

    int kt = blockIdx.x, qt = blockIdx.y, bh = blockIdx.z;
    int b = bh / H, h = bh % H;
    int tid = threadIdx.x;
    int wid = tid >> 5, lane = tid & 31;

    {
        const __nv_bfloat16* qhb = g_qh + (size_t)(b * L + qt * 128) * D + h * DK;
        const __nv_bfloat16* qlb = g_ql + (size_t)(b * L + qt * 128) * D + h * DK;
        const __nv_bfloat16* khb = g_kh + (size_t)(b * L + kt * 256) * D + h * DK;
        const __nv_bfloat16* klb = g_kl + (size_t)(b * L + kt * 256) * D + h * DK;

        #pragma unroll
        for (int it = 0; it < 2; it++) {          // Q: 128 rows
            int idx = tid + it * 512;
            int row = idx >> 3;
            int c8  = (idx & 7) * 8;
            *(uint4*)(sQh + row * RP + c8) = *(const uint4*)(qhb + (size_t)row * D + c8);
            *(uint4*)(sQl + row * RP + c8) = *(const uint4*)(qlb + (size_t)row * D + c8);
        }
        #pragma unroll
        for (int it = 0; it < 4; it++) {          // K: 256 rows
            int idx = tid + it * 512;
            int row = idx >> 3;
            int c8  = (idx & 7) * 8;
            *(uint4*)(sKh + row * RP + c8) = *(const uint4*)(khb + (size_t)row * D + c8);
            *(uint4*)(sKl + row * RP + c8) = *(const uint4*)(klb + (size_t)row * D + c8);
        }
    }
    __syncthreads();

    int wm = (wid & 1) * 64;
    int wn = (wid >> 1) * 32;

    float acc[4][4][4];
    #pragma unroll
    for (int i = 0; i < 4; i++)
        #pragma unroll
        for (int j = 0; j < 4; j++)
            #pragma unroll
            for (int r = 0; r < 4; r++) acc[i][j][r] = 0.f;

    uint32_t sQh_b = smem_u32(sQh), sQl_b = smem_u32(sQl);
    uint32_t sKh_b = smem_u32(sKh), sKl_b = smem_u32(sKl);

    int a_row = lane & 15;
    int a_kh8 = (lane >> 4) * 8;
    int b_row = lane & 7;
    int b_kh8 = ((lane >> 3) & 1) * 8;

    #pragma unroll
    for (int ks = 0; ks < 4; ks++) {
        int kb = ks * 16;
        uint32_t ah[4][4], al[4][4];
        #pragma unroll
        for (int i = 0; i < 4; i++) {
            uint32_t off = (uint32_t)((wm + i * 16 + a_row) * RP + kb + a_kh8) * 2;
            ldsm_x4(sQh_b + off, ah[i][0], ah[i][1], ah[i][2], ah[i][3]);
            ldsm_x4(sQl_b + off, al[i][0], al[i][1], al[i][2], al[i][3]);
        }
        #pragma unroll
        for (int j = 0; j < 4; j++) {
            uint32_t off = (uint32_t)((wn + j * 8 + b_row) * RP + kb + b_kh8) * 2;
            uint32_t bh2[2], bl2[2];
            ldsm_x2(sKh_b + off, bh2[0], bh2[1]);
            ldsm_x2(sKl_b + off, bl2[0], bl2[1]);
            #pragma unroll
            for (int i = 0; i < 4; i++) {
                mma_bf16(acc[i][j], ah[i], bh2);
                mma_bf16(acc[i][j], ah[i], bl2);
                mma_bf16(acc[i][j], al[i], bh2);
            }
        }
    }

    const float scale = 1.0f / 16.0f;     // 1/(2*sqrt(dk)), folds entmax z = s/2
    int r0 = lane >> 2;
    int cp = (lane & 3) * 2;
    #pragma unroll
    for (int i = 0; i < 4; i++) {
        int grow0 = qt * 128 + wm + i * 16 + r0;
        #pragma unroll
        for (int j = 0; j < 4; j++) {
            int gcol = kt * 256 + wn + j * 8 + cp;
            float2 v0 = make_float2(acc[i][j][0] * scale, acc[i][j][1] * scale);
            float2 v1 = make_float2(acc[i][j][2] * scale, acc[i][j][3] * scale);
            *(float2*)(g_s + ((size_t)bh * L + grow0) * L + gcol) = v0;
            *(float2*)(g_s + ((size_t)bh * L + grow0 + 8) * L + gcol) = v1;
        }
    }
}

// ---------------------------------------------------------------------------
// Phase 3: entmax-1.5, one WARP per (b,q) row; shuffle-only Newton.
// ---------------------------------------------------------------------------
__global__ void entmax_warp_kernel(const int* __restrict__ mask, float* __restrict__ out)
{
    int warp = (blockIdx.x * blockDim.x + threadIdx.x) >> 5;
    int lane = threadIdx.x & 31;
    int b = warp / L, qi = warp % L;

    unsigned long long vbits = 0ull;
    {
        const int4* mrow = (const int4*)(mask + b * L);
        #pragma unroll
        for (int i = 0; i < 12; i++) {
            int4 mv = mrow[lane + i * 32];
            if (mv.x) vbits |= 1ull << (i * 4 + 0);
            if (mv.y) vbits |= 1ull << (i * 4 + 1);
            if (mv.z) vbits |= 1ull << (i * 4 + 2);
            if (mv.w) vbits |= 1ull << (i * 4 + 3);
        }
    }

    float acc[48];
    #pragma unroll
    for (int e = 0; e < 48; e++) acc[e] = 0.f;

    const float invH = 1.0f / 12.0f;

    for (int h = 0; h < H; h++) {
        const float4* row = (const float4*)(g_s + ((size_t)(b * H + h) * L + qi) * L);
        float z[48];
        float m = -1e30f;
        #pragma unroll
        for (int i = 0; i < 12; i++) {
            float4 v = __ldg(row + lane + i * 32);
            z[i * 4 + 0] = (vbits >> (i * 4 + 0)) & 1 ? v.x : -1e30f;
            z[i * 4 + 1] = (vbits >> (i * 4 + 1)) & 1 ? v.y : -1e30f;
            z[i * 4 + 2] = (vbits >> (i * 4 + 2)) & 1 ? v.z : -1e30f;
            z[i * 4 + 3] = (vbits >> (i * 4 + 3)) & 1 ? v.w : -1e30f;
            m = fmaxf(m, fmaxf(fmaxf(z[i * 4], z[i * 4 + 1]), fmaxf(z[i * 4 + 2], z[i * 4 + 3])));
        }
        #pragma unroll
        for (int o = 16; o; o >>= 1) m = fmaxf(m, __shfl_xor_sync(0xffffffffu, m, o));

        float tau = m - 1.0f;

        for (int it = 0; it < 24; it++) {
            float s0 = 0.f, s1 = 0.f;
            #pragma unroll
            for (int e = 0; e < 48; e++) {
                float d = z[e] - tau;
                if (d > 0.f) { s0 = fmaf(d, d, s0); s1 += d; }
            }
            #pragma unroll
            for (int o = 16; o; o >>= 1) {
                s0 += __shfl_xor_sync(0xffffffffu, s0, o);
                s1 += __shfl_xor_sync(0xffffffffu, s1, o);
            }
            if (s1 <= 0.f) break;
            float step = (s0 - 1.0f) / (2.0f * s1);
            tau += step;
            if (fabsf(step) <= 5e-7f) break;
        }

        #pragma unroll
        for (int e = 0; e < 48; e++) {
            float d = z[e] - tau;
            if (d > 0.f) acc[e] = fmaf(d * d, invH, acc[e]);
        }
    }

    float4* orow = (float4*)(out + ((size_t)b * L + qi) * L);
    #pragma unroll
    for (int i = 0; i < 12; i++) {
        float4 v;
        v.x = acc[i * 4 + 0]; v.y = acc[i * 4 + 1];
        v.z = acc[i * 4 + 2]; v.w = acc[i * 4 + 3];
        orow[lane + i * 32] = v;
    }
}

// ---------------------------------------------------------------------------
extern "C" void kernel_launch(void* const* d_in, const int* in_sizes, int n_in,
                              void* d_out, int out_size)
{
    const float* query = (const float*)d_in[0];
    const float* key   = (const float*)d_in[1];
    const int*   mask  = (const int*)d_in[2];
    const float* wq_w  = (const float*)d_in[3];
    const float* wq_b  = (const float*)d_in[4];
    const float* wk_w  = (const float*)d_in[5];
    const float* wk_b  = (const float*)d_in[6];
    float* out = (float*)d_out;

    (void)in_sizes; (void)n_in; (void)out_size;

    cudaFuncSetAttribute(proj_mma_kernel,
                         cudaFuncAttributeMaxDynamicSharedMemorySize, PROJ_SM_BYTES);
    cudaFuncSetAttribute(scores_mma_kernel,
                         cudaFuncAttributeMaxDynamicSharedMemorySize, SC_SM_BYTES);

    {
        int n4_x = (int)(BLD / 4);
        int n4_w = (int)(DD / 4);
        split_src_kernel<<<(n4_x + 255) / 256, 256>>>(query, 0, n4_x);
        split_src_kernel<<<(n4_x + 255) / 256, 256>>>(key,   1, n4_x);
        split_src_kernel<<<(n4_w + 255) / 256, 256>>>(wq_w,  2, n4_w);
        split_src_kernel<<<(n4_w + 255) / 256, 256>>>(wk_w,  3, n4_w);
    }

    dim3 pgrid(D / 256, (B * L) / 128, 2);       // (3, 24, 2)
    proj_mma_kernel<<<pgrid, 512, PROJ_SM_BYTES>>>(wq_b, wk_b);

    dim3 sgrid(L / 256, L / 128, B * H);         // (6, 12, 24)
    scores_mma_kernel<<<sgrid, 512, SC_SM_BYTES>>>();

    entmax_warp_kernel<<<(B * L) / 4, 128>>>(mask, out);
}